// round 5
// baseline (speedup 1.0000x reference)
#include <cuda_runtime.h>

// AtteMatchLay: multi-perspective cosine matching. N=8192 rows, D=768, P=20.
// out[n,p] = dot/(max(sqrt(n1),eps)*max(sqrt(n2),eps)), sums over d weighted by w[p,d]^2.
//
// Round-5: cp.async 5-stage smem pipeline for the r/m streams (latency decoupling).
// Block = 256 thr = 8 warps = 4 row-pairs x 2 P-groups (8 rows/block, data staged once).
// Warp-tile = 2 rows (f32x2-packed) x 10 perspectives; w2 via L1-resident LDG.

#define PDIM   20
#define DDIM   768
#define PP     10
#define EPS    1e-8f
#define STAGES 5
#define DSEG   64           // d-columns per stage
#define NITER  (DDIM / DSEG) // 12

typedef unsigned long long ull;

// ---- packed f32x2 helpers (only reachable via PTX) ----
__device__ __forceinline__ ull pack2(float x) {
    ull r; asm("mov.b64 %0, {%1, %1};" : "=l"(r) : "f"(x)); return r;
}
__device__ __forceinline__ ull packab(float a, float b) {
    ull r; asm("mov.b64 %0, {%1, %2};" : "=l"(r) : "f"(a), "f"(b)); return r;
}
__device__ __forceinline__ float2 u2f(ull v) {
    float2 f; asm("mov.b64 {%0, %1}, %2;" : "=f"(f.x), "=f"(f.y) : "l"(v)); return f;
}
__device__ __forceinline__ ull mul2(ull a, ull b) {
    ull r; asm("mul.rn.f32x2 %0, %1, %2;" : "=l"(r) : "l"(a), "l"(b)); return r;
}
__device__ __forceinline__ void fma2(ull& acc, ull a, ull b) {
    asm("fma.rn.f32x2 %0, %1, %2, %0;" : "+l"(acc) : "l"(a), "l"(b));
}
__device__ __forceinline__ ull add2(ull a, ull b) {
    ull r; asm("add.rn.f32x2 %0, %1, %2;" : "=l"(r) : "l"(a), "l"(b)); return r;
}

// ---- cp.async helpers ----
__device__ __forceinline__ void cp_async16(void* smem_dst, const void* gmem_src) {
    unsigned sa = (unsigned)__cvta_generic_to_shared(smem_dst);
    asm volatile("cp.async.cg.shared.global [%0], [%1], 16;\n"
                 :: "r"(sa), "l"(gmem_src) : "memory");
}
__device__ __forceinline__ void cp_commit() {
    asm volatile("cp.async.commit_group;\n" ::: "memory");
}
template <int NMax>
__device__ __forceinline__ void cp_wait() {
    asm volatile("cp.async.wait_group %0;\n" :: "n"(NMax) : "memory");
}

// Squared weights, plain [P][D] float layout (61.5 KB, L1-resident).
__device__ float g_w2[PDIM * DDIM];

__global__ void prep_w2_kernel(const float* __restrict__ weight) {
    int t = blockIdx.x * blockDim.x + threadIdx.x;
    if (t < PDIM * DDIM) {
        float w = weight[t];
        g_w2[t] = w * w;
    }
}

__global__ void __launch_bounds__(256)
cosmatch_kernel(const float* __restrict__ repres,
                const float* __restrict__ max_att,
                float* __restrict__ out,
                int N) {
    // Pipeline buffers: [stage][array(r/m)][row-in-block][d-seg]
    __shared__ float sm[STAGES][2][8][DSEG];   // 20 KB

    const int tid  = threadIdx.x;
    const int warp = tid >> 5;
    const int lane = tid & 31;
    const int pg   = warp & 1;          // perspective group (0/1)
    const int rq   = warp >> 1;         // row pair within block (0..3)
    const int blockrow = blockIdx.x * 8;

    // cp.async producer mapping: 256 threads x 16B = 4KB per stage
    const int a   = tid >> 7;           // 0 = repres, 1 = max_att
    const int rem = tid & 127;
    const int ldr = rem >> 4;           // row in block (0..7)
    const int seg = rem & 15;           // 16B segment (4 floats)
    int grow = blockrow + ldr; if (grow >= N) grow = N - 1;  // clamp (tail-safe)
    const float* srcbase = (a == 0 ? repres : max_att) + (size_t)grow * DDIM + seg * 4;

    // Prologue: issue stages 0..STAGES-2
#pragma unroll
    for (int s = 0; s < STAGES - 1; s++) {
        cp_async16(&sm[s][a][ldr][seg * 4], srcbase + s * DSEG);
        cp_commit();
    }

    const float* wg = g_w2 + pg * PP * DDIM;
    const int d0 = lane * 2;            // d offset within a stage

    ull accd[PP], accr[PP], accm[PP];
#pragma unroll
    for (int p = 0; p < PP; p++) { accd[p] = 0ull; accr[p] = 0ull; accm[p] = 0ull; }

    for (int k = 0; k < NITER; k++) {
        cp_wait<STAGES - 2>();          // stage k resident
        __syncthreads();

        // Refill: stage k+STAGES-1 overwrites buffer (k-1)%STAGES (readers done)
        if (k + STAGES - 1 < NITER) {
            const int s = (k + STAGES - 1) % STAGES;
            cp_async16(&sm[s][a][ldr][seg * 4], srcbase + (k + STAGES - 1) * DSEG);
        }
        cp_commit();

        const int buf = k % STAGES;
        const int r0 = rq * 2, r1 = r0 + 1;
        const float2 R0 = *(const float2*)&sm[buf][0][r0][d0];
        const float2 R1 = *(const float2*)&sm[buf][0][r1][d0];
        const float2 M0 = *(const float2*)&sm[buf][1][r0][d0];
        const float2 M1 = *(const float2*)&sm[buf][1][r1][d0];

        const ull ra0 = packab(R0.x, R1.x), ra1 = packab(R0.y, R1.y);
        const ull ma0 = packab(M0.x, M1.x), ma1 = packab(M0.y, M1.y);
        const ull rm0 = mul2(ra0, ma0), rm1 = mul2(ra1, ma1);
        const ull rr0 = mul2(ra0, ra0), rr1 = mul2(ra1, ra1);
        const ull mm0 = mul2(ma0, ma0), mm1 = mul2(ma1, ma1);

        const float* wk = wg + k * DSEG + d0;
#pragma unroll
        for (int p = 0; p < PP; p++) {
            const float2 w = *(const float2*)(wk + p * DDIM);
            const ull wx = pack2(w.x);
            const ull wy = pack2(w.y);
            fma2(accd[p], rm0, wx);
            fma2(accd[p], rm1, wy);
            fma2(accr[p], rr0, wx);
            fma2(accr[p], rr1, wy);
            fma2(accm[p], mm0, wx);
            fma2(accm[p], mm1, wy);
        }
        __syncthreads();   // all reads of buf k done before iter k+1 overwrites buf k%S... (k+S)%S
    }

    // Butterfly reduction across lanes (accumulators stay row-packed)
#pragma unroll
    for (int mask = 16; mask > 0; mask >>= 1) {
#pragma unroll
        for (int p = 0; p < PP; p++) {
            accd[p] = add2(accd[p], (ull)__shfl_xor_sync(0xFFFFFFFFu, accd[p], mask));
            accr[p] = add2(accr[p], (ull)__shfl_xor_sync(0xFFFFFFFFu, accr[p], mask));
            accm[p] = add2(accm[p], (ull)__shfl_xor_sync(0xFFFFFFFFu, accm[p], mask));
        }
    }

    // Epilogue: lane 0 writes 2 rows x 10 perspectives
    const int rowbase = blockrow + rq * 2;
    if (lane == 0 && rowbase < N) {
        float* o0 = out + (size_t)(rowbase + 0) * PDIM + pg * PP;
        float* o1 = out + (size_t)(rowbase + 1) * PDIM + pg * PP;
#pragma unroll
        for (int p = 0; p < PP; p++) {
            const float2 dd = u2f(accd[p]);
            const float2 n1 = u2f(accr[p]);
            const float2 n2 = u2f(accm[p]);
            o0[p] = dd.x / (fmaxf(sqrtf(n1.x), EPS) * fmaxf(sqrtf(n2.x), EPS));
            o1[p] = dd.y / (fmaxf(sqrtf(n1.y), EPS) * fmaxf(sqrtf(n2.y), EPS));
        }
    }
}

extern "C" void kernel_launch(void* const* d_in, const int* in_sizes, int n_in,
                              void* d_out, int out_size) {
    const float* repres  = (const float*)d_in[0];
    const float* max_att = (const float*)d_in[1];
    const float* weight  = (const float*)d_in[2];
    float* out = (float*)d_out;

    const int N = in_sizes[0] / DDIM;   // 8192 rows for the given shapes

    {
        const int total = PDIM * DDIM;
        prep_w2_kernel<<<(total + 255) / 256, 256>>>(weight);
    }
    {
        // 8 rows per block (8 warps: 4 row-pairs x 2 P-groups)
        const int blocks = (N + 7) / 8;
        cosmatch_kernel<<<blocks, 256>>>(repres, max_att, out, N);
    }
}

// round 6
// speedup vs baseline: 1.1345x; 1.1345x over previous
#include <cuda_runtime.h>

// AtteMatchLay: multi-perspective cosine matching. N=8192 rows, D=768, P=20.
// out[n,p] = dot/(max(sqrt(n1),eps)*max(sqrt(n2),eps)), sums over d weighted by w[p,d]^2.
//
// Round-6: barrier-free, fully unrolled, explicit 2-stage register prefetch of the
// r/m data streams. Warp-tile = 2 rows (f32x2 row-packed) x 10 perspectives.
// Block = 128 thr = 4 warps = 2 row-pairs x 2 P-groups; pg pair shares rows via L2.

#define PDIM  20
#define DDIM  768
#define PP    10
#define NITER (DDIM / 64)   // 12
#define EPS   1e-8f

typedef unsigned long long ull;

// ---- packed f32x2 helpers (only reachable via PTX) ----
__device__ __forceinline__ ull pack2(float x) {
    ull r; asm("mov.b64 %0, {%1, %1};" : "=l"(r) : "f"(x)); return r;
}
__device__ __forceinline__ ull packab(float a, float b) {
    ull r; asm("mov.b64 %0, {%1, %2};" : "=l"(r) : "f"(a), "f"(b)); return r;
}
__device__ __forceinline__ float2 u2f(ull v) {
    float2 f; asm("mov.b64 {%0, %1}, %2;" : "=f"(f.x), "=f"(f.y) : "l"(v)); return f;
}
__device__ __forceinline__ ull mul2(ull a, ull b) {
    ull r; asm("mul.rn.f32x2 %0, %1, %2;" : "=l"(r) : "l"(a), "l"(b)); return r;
}
__device__ __forceinline__ void fma2(ull& acc, ull a, ull b) {
    asm("fma.rn.f32x2 %0, %1, %2, %0;" : "+l"(acc) : "l"(a), "l"(b));
}
__device__ __forceinline__ ull add2(ull a, ull b) {
    ull r; asm("add.rn.f32x2 %0, %1, %2;" : "=l"(r) : "l"(a), "l"(b)); return r;
}

// Squared weights, [P][D] float layout (61.5 KB, L1/L2-resident).
__device__ float g_w2[PDIM * DDIM];

__global__ void prep_w2_kernel(const float* __restrict__ weight) {
    int t = blockIdx.x * blockDim.x + threadIdx.x;
    if (t < PDIM * DDIM) {
        float w = weight[t];
        g_w2[t] = w * w;
    }
}

__global__ void __launch_bounds__(128)
cosmatch_kernel(const float* __restrict__ repres,
                const float* __restrict__ max_att,
                float* __restrict__ out,
                int N) {
    const int tid  = threadIdx.x;
    const int warp = tid >> 5;
    const int lane = tid & 31;
    const int pg   = warp & 1;        // perspective group (0/1)
    const int rq   = warp >> 1;       // row pair within block (0/1)
    const int rowbase = blockIdx.x * 4 + rq * 2;

    const float* rp = repres  + (size_t)rowbase * DDIM + lane * 2;
    const float* mp = max_att + (size_t)rowbase * DDIM + lane * 2;
    const float* wg = g_w2 + pg * PP * DDIM + lane * 2;

    ull accd[PP], accr[PP], accm[PP];
#pragma unroll
    for (int p = 0; p < PP; p++) { accd[p] = 0ull; accr[p] = 0ull; accm[p] = 0ull; }

    // 2-stage data prefetch buffers (row0/row1 of r and m)
    float2 PR0[2], PR1[2], PM0[2], PM1[2];
#pragma unroll
    for (int s = 0; s < 2; s++) {
        PR0[s] = *(const float2*)(rp + s * 64);
        PR1[s] = *(const float2*)(rp + DDIM + s * 64);
        PM0[s] = *(const float2*)(mp + s * 64);
        PM1[s] = *(const float2*)(mp + DDIM + s * 64);
    }

#pragma unroll
    for (int k = 0; k < NITER; k++) {
        const int buf = k & 1;

        // Consume current stage into packed operands
        const float2 R0 = PR0[buf], R1 = PR1[buf];
        const float2 M0 = PM0[buf], M1 = PM1[buf];

        // Issue loads for iteration k+2 immediately (deep prefetch, pre-FMA)
        if (k + 2 < NITER) {
            const int d = (k + 2) * 64;
            PR0[buf] = *(const float2*)(rp + d);
            PR1[buf] = *(const float2*)(rp + DDIM + d);
            PM0[buf] = *(const float2*)(mp + d);
            PM1[buf] = *(const float2*)(mp + DDIM + d);
        }

        const ull ra0 = packab(R0.x, R1.x), ra1 = packab(R0.y, R1.y);
        const ull ma0 = packab(M0.x, M1.x), ma1 = packab(M0.y, M1.y);
        const ull rm0 = mul2(ra0, ma0), rm1 = mul2(ra1, ma1);
        const ull rr0 = mul2(ra0, ra0), rr1 = mul2(ra1, ra1);
        const ull mm0 = mul2(ma0, ma0), mm1 = mul2(ma1, ma1);

        const float* wk = wg + k * 64;
#pragma unroll
        for (int p = 0; p < PP; p++) {
            const float2 w = *(const float2*)(wk + p * DDIM);
            const ull wx = pack2(w.x);
            const ull wy = pack2(w.y);
            fma2(accd[p], rm0, wx);
            fma2(accd[p], rm1, wy);
            fma2(accr[p], rr0, wx);
            fma2(accr[p], rr1, wy);
            fma2(accm[p], mm0, wx);
            fma2(accm[p], mm1, wy);
        }
    }

    // Butterfly reduction across lanes (accumulators stay row-packed)
#pragma unroll
    for (int mask = 16; mask > 0; mask >>= 1) {
#pragma unroll
        for (int p = 0; p < PP; p++) {
            accd[p] = add2(accd[p], (ull)__shfl_xor_sync(0xFFFFFFFFu, accd[p], mask));
            accr[p] = add2(accr[p], (ull)__shfl_xor_sync(0xFFFFFFFFu, accr[p], mask));
            accm[p] = add2(accm[p], (ull)__shfl_xor_sync(0xFFFFFFFFu, accm[p], mask));
        }
    }

    // Epilogue: lane 0 writes 2 rows x 10 perspectives
    if (lane == 0) {
        float* o0 = out + (size_t)(rowbase + 0) * PDIM + pg * PP;
        float* o1 = out + (size_t)(rowbase + 1) * PDIM + pg * PP;
#pragma unroll
        for (int p = 0; p < PP; p++) {
            const float2 dd = u2f(accd[p]);
            const float2 n1 = u2f(accr[p]);
            const float2 n2 = u2f(accm[p]);
            o0[p] = dd.x / (fmaxf(sqrtf(n1.x), EPS) * fmaxf(sqrtf(n2.x), EPS));
            o1[p] = dd.y / (fmaxf(sqrtf(n1.y), EPS) * fmaxf(sqrtf(n2.y), EPS));
        }
    }
}

extern "C" void kernel_launch(void* const* d_in, const int* in_sizes, int n_in,
                              void* d_out, int out_size) {
    const float* repres  = (const float*)d_in[0];
    const float* max_att = (const float*)d_in[1];
    const float* weight  = (const float*)d_in[2];
    float* out = (float*)d_out;

    const int N = in_sizes[0] / DDIM;   // 8192 rows for the given shapes

    {
        const int total = PDIM * DDIM;
        prep_w2_kernel<<<(total + 255) / 256, 256>>>(weight);
    }
    {
        // 4 rows per block (4 warps: 2 row-pairs x 2 P-groups)
        const int blocks = (N + 3) / 4;
        cosmatch_kernel<<<blocks, 128>>>(repres, max_att, out, N);
    }
}

// round 7
// speedup vs baseline: 1.2597x; 1.1104x over previous
#include <cuda_runtime.h>

// AtteMatchLay: multi-perspective cosine matching. N=8192 rows, D=768, P=20.
// out[n,p] = dot/(max(sqrt(n1),eps)*max(sqrt(n2),eps)), sums over d weighted by w[p,d]^2.
//
// Round-7: R6's explicit 2-stage register prefetch, but unroll-2 (not full) and
// __launch_bounds__(128,4) to cap regs <=128 -> 16 warps/SM (was 7.4 at 170 regs).
// Warp-tile = 2 rows (f32x2 row-packed) x 10 perspectives; branch-free prefetch.

#define PDIM  20
#define DDIM  768
#define PP    10
#define NITER (DDIM / 64)   // 12
#define EPS   1e-8f

typedef unsigned long long ull;

// ---- packed f32x2 helpers (only reachable via PTX) ----
__device__ __forceinline__ ull pack2(float x) {
    ull r; asm("mov.b64 %0, {%1, %1};" : "=l"(r) : "f"(x)); return r;
}
__device__ __forceinline__ ull packab(float a, float b) {
    ull r; asm("mov.b64 %0, {%1, %2};" : "=l"(r) : "f"(a), "f"(b)); return r;
}
__device__ __forceinline__ float2 u2f(ull v) {
    float2 f; asm("mov.b64 {%0, %1}, %2;" : "=f"(f.x), "=f"(f.y) : "l"(v)); return f;
}
__device__ __forceinline__ ull mul2(ull a, ull b) {
    ull r; asm("mul.rn.f32x2 %0, %1, %2;" : "=l"(r) : "l"(a), "l"(b)); return r;
}
__device__ __forceinline__ void fma2(ull& acc, ull a, ull b) {
    asm("fma.rn.f32x2 %0, %1, %2, %0;" : "+l"(acc) : "l"(a), "l"(b));
}
__device__ __forceinline__ ull add2(ull a, ull b) {
    ull r; asm("add.rn.f32x2 %0, %1, %2;" : "=l"(r) : "l"(a), "l"(b)); return r;
}

// Squared weights, [P][D] float layout (61.5 KB, L1/L2-resident).
__device__ float g_w2[PDIM * DDIM];

__global__ void prep_w2_kernel(const float* __restrict__ weight) {
    int t = blockIdx.x * blockDim.x + threadIdx.x;
    if (t < PDIM * DDIM) {
        float w = weight[t];
        g_w2[t] = w * w;
    }
}

__global__ void __launch_bounds__(128, 4)
cosmatch_kernel(const float* __restrict__ repres,
                const float* __restrict__ max_att,
                float* __restrict__ out,
                int N) {
    const int tid  = threadIdx.x;
    const int warp = tid >> 5;
    const int lane = tid & 31;
    const int pg   = warp & 1;        // perspective group (0/1)
    const int rq   = warp >> 1;       // row pair within block (0/1)
    const int rowbase = blockIdx.x * 4 + rq * 2;

    const float* rp = repres  + (size_t)rowbase * DDIM + lane * 2;
    const float* mp = max_att + (size_t)rowbase * DDIM + lane * 2;
    const float* wg = g_w2 + pg * PP * DDIM + lane * 2;

    ull accd[PP], accr[PP], accm[PP];
#pragma unroll
    for (int p = 0; p < PP; p++) { accd[p] = 0ull; accr[p] = 0ull; accm[p] = 0ull; }

    // 2-stage data prefetch buffers (row0/row1 of r and m)
    float2 PR0[2], PR1[2], PM0[2], PM1[2];
#pragma unroll
    for (int s = 0; s < 2; s++) {
        PR0[s] = *(const float2*)(rp + s * 64);
        PR1[s] = *(const float2*)(rp + DDIM + s * 64);
        PM0[s] = *(const float2*)(mp + s * 64);
        PM1[s] = *(const float2*)(mp + DDIM + s * 64);
    }

#pragma unroll 2
    for (int k = 0; k < NITER; k++) {
        const int buf = k & 1;

        // Consume current stage into packed operands
        const float2 R0 = PR0[buf], R1 = PR1[buf];
        const float2 M0 = PM0[buf], M1 = PM1[buf];

        // Branch-free deep prefetch for iteration k+2 (clamped; tail re-reads are harmless)
        {
            int kp = k + 2; if (kp > NITER - 1) kp = NITER - 1;
            const int d = kp * 64;
            PR0[buf] = *(const float2*)(rp + d);
            PR1[buf] = *(const float2*)(rp + DDIM + d);
            PM0[buf] = *(const float2*)(mp + d);
            PM1[buf] = *(const float2*)(mp + DDIM + d);
        }

        const ull ra0 = packab(R0.x, R1.x), ra1 = packab(R0.y, R1.y);
        const ull ma0 = packab(M0.x, M1.x), ma1 = packab(M0.y, M1.y);
        const ull rm0 = mul2(ra0, ma0), rm1 = mul2(ra1, ma1);
        const ull rr0 = mul2(ra0, ra0), rr1 = mul2(ra1, ra1);
        const ull mm0 = mul2(ma0, ma0), mm1 = mul2(ma1, ma1);

        const float* wk = wg + k * 64;
#pragma unroll
        for (int p = 0; p < PP; p++) {
            const float2 w = *(const float2*)(wk + p * DDIM);
            const ull wx = pack2(w.x);
            const ull wy = pack2(w.y);
            fma2(accd[p], rm0, wx);
            fma2(accd[p], rm1, wy);
            fma2(accr[p], rr0, wx);
            fma2(accr[p], rr1, wy);
            fma2(accm[p], mm0, wx);
            fma2(accm[p], mm1, wy);
        }
    }

    // Butterfly reduction across lanes (accumulators stay row-packed)
#pragma unroll
    for (int mask = 16; mask > 0; mask >>= 1) {
#pragma unroll
        for (int p = 0; p < PP; p++) {
            accd[p] = add2(accd[p], (ull)__shfl_xor_sync(0xFFFFFFFFu, accd[p], mask));
            accr[p] = add2(accr[p], (ull)__shfl_xor_sync(0xFFFFFFFFu, accr[p], mask));
            accm[p] = add2(accm[p], (ull)__shfl_xor_sync(0xFFFFFFFFu, accm[p], mask));
        }
    }

    // Epilogue: lane 0 writes 2 rows x 10 perspectives
    if (lane == 0) {
        float* o0 = out + (size_t)(rowbase + 0) * PDIM + pg * PP;
        float* o1 = out + (size_t)(rowbase + 1) * PDIM + pg * PP;
#pragma unroll
        for (int p = 0; p < PP; p++) {
            const float2 dd = u2f(accd[p]);
            const float2 n1 = u2f(accr[p]);
            const float2 n2 = u2f(accm[p]);
            o0[p] = dd.x / (fmaxf(sqrtf(n1.x), EPS) * fmaxf(sqrtf(n2.x), EPS));
            o1[p] = dd.y / (fmaxf(sqrtf(n1.y), EPS) * fmaxf(sqrtf(n2.y), EPS));
        }
    }
}

extern "C" void kernel_launch(void* const* d_in, const int* in_sizes, int n_in,
                              void* d_out, int out_size) {
    const float* repres  = (const float*)d_in[0];
    const float* max_att = (const float*)d_in[1];
    const float* weight  = (const float*)d_in[2];
    float* out = (float*)d_out;

    const int N = in_sizes[0] / DDIM;   // 8192 rows for the given shapes

    {
        const int total = PDIM * DDIM;
        prep_w2_kernel<<<(total + 255) / 256, 256>>>(weight);
    }
    {
        // 4 rows per block (4 warps: 2 row-pairs x 2 P-groups)
        const int blocks = (N + 3) / 4;
        cosmatch_kernel<<<blocks, 128>>>(repres, max_att, out, N);
    }
}